// round 8
// baseline (speedup 1.0000x reference)
#include <cuda_runtime.h>
#include <cuda_bf16.h>

// ---------------------------------------------------------------------------
// NT-Xent loss, N=8192, D=512. INT8 (x127) mma.sync m16n8k32 (s8 IMMA),
// upper-triangular block tiles only (S = Z Z^T symmetric).
// Tile (I,J), J>I: exp-row-sums -> rows of block I, exp-col-sums -> block J.
// loss_i = (1 - pos_i)/tau + log( sum_{j != i} exp((dot_ij - 1)/tau) )
// 296 CTAs, 2 CTAs/SM. Final logsumexp fused into the GEMM kernel via an
// atomic completion ticket (last CTA reduces).
// ---------------------------------------------------------------------------

#define NN      8192
#define DD      512
#define BHALF   4096
#define NCHUNK  4            // 512 bytes / 128-byte chunk
#define NTILES  2080
#define NCTAS   296

#define K1F     20.60992915555662f              // log2(e)/0.07
#define EXSC    (20.60992915555662f/16129.0f)   // K1F / 127^2
#define PSC     (1.0f/16129.0f)                 // 1/127^2
#define INV_TAU 14.285714285714286f

#define A_BYTES  65536       // 128 rows x 512 B (4 chunks x 16 KB)
#define B_OFF    65536
#define B_BYTES  16384       // one B chunk: 128 rows x 128 B
#define SMEM_BYTES (A_BYTES + 2*B_BYTES + 1024)

__device__ __align__(128) signed char g_z[(size_t)NN * DD];   // int8, x127
__device__ float g_rowsum[NN];
__device__ float g_pos[NN];
__device__ unsigned g_done;

// ------------------------------- helpers -----------------------------------
__device__ __forceinline__ unsigned smem_u32(const void* p) {
    unsigned a;
    asm("{ .reg .u64 t; cvta.to.shared.u64 t, %1; cvt.u32.u64 %0, t; }"
        : "=r"(a) : "l"(p));
    return a;
}
__device__ __forceinline__ unsigned swz(unsigned off) {
    return off ^ ((off >> 3) & 0x70);
}
__device__ __forceinline__ void cp16(unsigned dst, const void* src) {
    asm volatile("cp.async.cg.shared.global [%0], [%1], 16;"
                 :: "r"(dst), "l"(src) : "memory");
}
#define CP_COMMIT() asm volatile("cp.async.commit_group;" ::: "memory")
#define CP_WAIT(n)  asm volatile("cp.async.wait_group %0;" :: "n"(n) : "memory")

__device__ __forceinline__ void ldsm_x4(unsigned* r, unsigned addr) {
    asm volatile("ldmatrix.sync.aligned.m8n8.x4.shared.b16 {%0,%1,%2,%3}, [%4];"
                 : "=r"(r[0]), "=r"(r[1]), "=r"(r[2]), "=r"(r[3]) : "r"(addr));
}
__device__ __forceinline__ void mma_s8(int* c, const unsigned* a,
                                       unsigned b0, unsigned b1) {
    asm volatile(
        "mma.sync.aligned.m16n8k32.row.col.satfinite.s32.s8.s8.s32 "
        "{%0,%1,%2,%3}, {%4,%5,%6,%7}, {%8,%9}, {%0,%1,%2,%3};"
        : "+r"(c[0]), "+r"(c[1]), "+r"(c[2]), "+r"(c[3])
        : "r"(a[0]), "r"(a[1]), "r"(a[2]), "r"(a[3]), "r"(b0), "r"(b1));
}
__device__ __forceinline__ float ex2s(int vi) {   // exp((v/127^2 - 1)/tau)
    float y;
    asm("ex2.approx.ftz.f32 %0, %1;" : "=f"(y) : "f"(fmaf((float)vi, EXSC, -K1F)));
    return y;
}

// decode flattened tile index -> (I, J)
__device__ __forceinline__ void tile_decode(int t, int& I, int& J) {
    int p = t / 65;
    int l = t - p * 65;
    int n1 = 64 - p;
    if (l < n1) { I = p;      J = p + l; }
    else        { I = 63 - p; J = I + (l - n1); }
}

// ------------------------- kernel 1: normalize -> int8 ---------------------
__global__ __launch_bounds__(256) void ntx_normalize(const float* __restrict__ anchor,
                                                     const float* __restrict__ positive) {
    int gt = blockIdx.x * 256 + threadIdx.x;
    if (gt < NN) g_rowsum[gt] = 0.f;          // graph-replay safe re-init
    if (gt == 0) g_done = 0u;

    int row  = blockIdx.x * 8 + (threadIdx.x >> 5);
    int lane = threadIdx.x & 31;
    const float* src = (row < BHALF) ? (anchor + (size_t)row * DD)
                                     : (positive + (size_t)(row - BHALF) * DD);
    const float4* s4 = (const float4*)src;
    float4 v[4];
    float ss = 0.f;
#pragma unroll
    for (int q = 0; q < 4; q++) {
        v[q] = s4[lane + 32 * q];
        ss += v[q].x * v[q].x + v[q].y * v[q].y + v[q].z * v[q].z + v[q].w * v[q].w;
    }
#pragma unroll
    for (int o = 16; o > 0; o >>= 1) ss += __shfl_xor_sync(0xFFFFFFFFu, ss, o);
    float s127 = 127.0f / fmaxf(sqrtf(ss), 1e-8f);   // |x_i| <= norm -> |q| <= 127

    unsigned* zp = (unsigned*)(g_z + (size_t)row * DD);
#pragma unroll
    for (int q = 0; q < 4; q++) {
        int i0 = __float2int_rn(v[q].x * s127);
        int i1 = __float2int_rn(v[q].y * s127);
        int i2 = __float2int_rn(v[q].z * s127);
        int i3 = __float2int_rn(v[q].w * s127);
        zp[lane + 32 * q] = (unsigned)(i0 & 0xFF) | ((unsigned)(i1 & 0xFF) << 8)
                          | ((unsigned)(i2 & 0xFF) << 16) | ((unsigned)i3 << 24);
    }
}

// ------------------------- kernel 2: upper-tri GEMM + exp-reduce -----------
__device__ __forceinline__ void issueB(unsigned bbase, int colbase, int k, int tid) {
#pragma unroll
    for (int it = 0; it < 4; it++) {
        int idx = tid + it * 256;
        int r = idx >> 3, c8 = idx & 7;
        const void* src = g_z + ((size_t)(colbase + r) << 9) + k * 128 + c8 * 16;
        cp16(bbase + swz((unsigned)(r * 128 + c8 * 16)), src);
    }
}

// ring depth 2: slot = m & 1
__device__ __forceinline__ void issue_chunk(unsigned Bb, int t0, int t1, int m, int tid) {
    int tt = t0 + (m >> 2);
    if (tt < t1) {
        int I2, J2;
        tile_decode(tt, I2, J2);
        issueB(Bb + (unsigned)(m & 1) * B_BYTES, J2 << 7, m & 3, tid);
    }
    CP_COMMIT();
}

__global__ __launch_bounds__(256, 2) void ntx_main(float* __restrict__ out) {
    extern __shared__ char smem_raw[];
    unsigned raw  = smem_u32(smem_raw);
    unsigned base = (raw + 1023u) & ~1023u;
    char* sp      = smem_raw + (base - raw);
    unsigned A  = base;
    unsigned Bb = base + B_OFF;

    int tid  = threadIdx.x;
    int wid  = tid >> 5, lane = tid & 31;
    int warpM = wid & 3, warpN = wid >> 2;     // 4 x 2 warp grid, tile 32x64
    int qrow = lane >> 2;

    int c  = blockIdx.x;
    int t0 = (c * NTILES) / NCTAS;
    int t1 = ((c + 1) * NTILES) / NCTAS;

    int sel = lane >> 3, lr = lane & 7;
    unsigned aoff[2][4];
#pragma unroll
    for (int mf = 0; mf < 2; mf++)
#pragma unroll
        for (int ks = 0; ks < 4; ks++) {
            int r = warpM * 32 + mf * 16 + ((sel & 1) << 3) + lr;
            unsigned cb = (unsigned)(ks * 32 + ((sel >> 1) << 4));
            aoff[mf][ks] = (unsigned)(r * 128) + (cb ^ ((unsigned)lr << 4));
        }
    unsigned boff[4][4];
#pragma unroll
    for (int p = 0; p < 4; p++)
#pragma unroll
        for (int ks = 0; ks < 4; ks++) {
            int r = warpN * 64 + p * 16 + ((sel & 1) << 3) + lr;
            unsigned cb = (unsigned)(ks * 32 + ((sel >> 1) << 4));
            boff[p][ks] = (unsigned)(r * 128) + (cb ^ ((unsigned)lr << 4));
        }

    issue_chunk(Bb, t0, t1, 0, tid);

    int acc[2][8][4];
    float rsum[2][2] = {{0.f, 0.f}, {0.f, 0.f}};
    int curI = -1;
    int cm = 0;

    for (int t = t0; t < t1; t++) {
        int I, J;
        tile_decode(t, I, J);
        int rowbase = I << 7, colbase = J << 7;

        if (I != curI) {
            if (curI >= 0) {
#pragma unroll
                for (int mf = 0; mf < 2; mf++)
#pragma unroll
                    for (int h = 0; h < 2; h++) {
                        float v = rsum[mf][h];
                        v += __shfl_xor_sync(0xFFFFFFFFu, v, 1);
                        v += __shfl_xor_sync(0xFFFFFFFFu, v, 2);
                        if ((lane & 3) == 0)
                            atomicAdd(&g_rowsum[(curI << 7) + warpM * 32 + mf * 16 + h * 8 + qrow], v);
                        rsum[mf][h] = 0.f;
                    }
            }
            __syncthreads();                   // all readers of old A done
#pragma unroll
            for (int it = 0; it < 16; it++) {
                int x = tid + it * 256;
                int r = x >> 5, u = x & 31, ck = u >> 3, c8 = u & 7;
                const uint4* src = (const uint4*)(g_z + ((size_t)(rowbase + r) << 9)
                                                  + ck * 128 + c8 * 16);
                *(uint4*)(sp + ck * 16384 + swz((unsigned)(r * 128 + c8 * 16))) = *src;
            }
            __syncthreads();
            curI = I;
        }

#pragma unroll
        for (int mf = 0; mf < 2; mf++)
#pragma unroll
            for (int nf = 0; nf < 8; nf++)
#pragma unroll
                for (int e = 0; e < 4; e++) acc[mf][nf][e] = 0;

#pragma unroll
        for (int k = 0; k < NCHUNK; k++) {
            CP_WAIT(0);
            __syncthreads();
            issue_chunk(Bb, t0, t1, cm + 1, tid);

            unsigned Ac = A + k * 16384;
            unsigned Bc = Bb + (unsigned)(cm & 1) * B_BYTES;
#pragma unroll
            for (int ks = 0; ks < 4; ks++) {
                unsigned afr[2][4];
                ldsm_x4(afr[0], Ac + aoff[0][ks]);
                ldsm_x4(afr[1], Ac + aoff[1][ks]);
                unsigned bfr[4][4];
#pragma unroll
                for (int p = 0; p < 4; p++) ldsm_x4(bfr[p], Bc + boff[p][ks]);
#pragma unroll
                for (int mf = 0; mf < 2; mf++)
#pragma unroll
                    for (int nf = 0; nf < 8; nf++)
                        mma_s8(acc[mf][nf], afr[mf],
                               bfr[nf >> 1][nf & 1],
                               bfr[nf >> 1][2 + (nf & 1)]);
            }
            cm++;
        }

        // ---- epilogue ----
        bool isdiag = (J == I);
        bool ispos  = (J == I + 32);

        if (isdiag | ispos) {
#pragma unroll
            for (int mf = 0; mf < 2; mf++)
#pragma unroll
                for (int h = 0; h < 2; h++) {
                    int rloc = warpM * 32 + mf * 16 + h * 8 + qrow;
                    int cc = rloc - warpN * 64;
                    if (cc >= 0 && cc < 64 && (((cc >> 1) & 3) == (lane & 3))) {
                        int v = acc[mf][cc >> 3][(h << 1) | (cc & 1)];
                        if (isdiag) rsum[mf][h] -= ex2s(v);
                        if (ispos) {
                            float pv = (float)v * PSC;
                            g_pos[rowbase + rloc] = pv;
                            g_pos[rowbase + rloc + BHALF] = pv;
                        }
                    }
                }
        }

        float colp[16];
#pragma unroll
        for (int q = 0; q < 16; q++) colp[q] = 0.f;
#pragma unroll
        for (int mf = 0; mf < 2; mf++) {
            float slo = 0.f, shi = 0.f;
#pragma unroll
            for (int nf = 0; nf < 8; nf++) {
                float e0 = ex2s(acc[mf][nf][0]);
                float e1 = ex2s(acc[mf][nf][1]);
                float e2 = ex2s(acc[mf][nf][2]);
                float e3 = ex2s(acc[mf][nf][3]);
                slo += e0 + e1;
                shi += e2 + e3;
                colp[nf * 2]     += e0 + e2;
                colp[nf * 2 + 1] += e1 + e3;
            }
            rsum[mf][0] += slo;
            rsum[mf][1] += shi;
        }

        if (!isdiag) {
#pragma unroll
            for (int q = 0; q < 16; q++) {
                float v = colp[q];
                v += __shfl_xor_sync(0xFFFFFFFFu, v, 4);
                v += __shfl_xor_sync(0xFFFFFFFFu, v, 8);
                v += __shfl_xor_sync(0xFFFFFFFFu, v, 16);
                if (lane < 4) {
                    int ccol = (q >> 1) * 8 + 2 * lane + (q & 1);
                    atomicAdd(&g_rowsum[colbase + warpN * 64 + ccol], v);
                }
            }
        }
    }

    // final row flush
#pragma unroll
    for (int mf = 0; mf < 2; mf++)
#pragma unroll
        for (int h = 0; h < 2; h++) {
            float v = rsum[mf][h];
            v += __shfl_xor_sync(0xFFFFFFFFu, v, 1);
            v += __shfl_xor_sync(0xFFFFFFFFu, v, 2);
            if ((lane & 3) == 0 && curI >= 0)
                atomicAdd(&g_rowsum[(curI << 7) + warpM * 32 + mf * 16 + h * 8 + qrow], v);
        }

    // ---- completion ticket: last CTA computes the loss ----
    __threadfence();
    __syncthreads();
    __shared__ unsigned ticket;
    if (tid == 0) ticket = atomicAdd(&g_done, 1u);
    __syncthreads();
    if (ticket == NCTAS - 1) {
        float local = 0.f;
        for (int r = tid; r < NN; r += 256)
            local += (1.0f - g_pos[r]) * INV_TAU + __logf(g_rowsum[r]);
#pragma unroll
        for (int o = 16; o > 0; o >>= 1) local += __shfl_xor_sync(0xFFFFFFFFu, local, o);
        __shared__ float red[8];
        if (lane == 0) red[wid] = local;
        __syncthreads();
        if (tid < 8) {
            float v = red[tid];
#pragma unroll
            for (int o = 4; o > 0; o >>= 1) v += __shfl_xor_sync(0xFFu, v, o);
            if (tid == 0) out[0] = v * (1.0f / (float)NN);
        }
    }
}

// ---------------------------------------------------------------------------
extern "C" void kernel_launch(void* const* d_in, const int* in_sizes, int n_in,
                              void* d_out, int out_size) {
    (void)in_sizes; (void)n_in; (void)out_size;
    const float* anchor   = (const float*)d_in[0];
    const float* positive = (const float*)d_in[1];

    cudaFuncSetAttribute(ntx_main, cudaFuncAttributeMaxDynamicSharedMemorySize,
                         SMEM_BYTES);

    ntx_normalize<<<NN / 8, 256>>>(anchor, positive);
    ntx_main<<<NCTAS, 256, SMEM_BYTES>>>((float*)d_out);
}

// round 9
// speedup vs baseline: 1.7761x; 1.7761x over previous
#include <cuda_runtime.h>
#include <cuda_bf16.h>

// ---------------------------------------------------------------------------
// NT-Xent loss, N=8192, D=512. FP8 (e4m3, scale 16) mma.sync m16n8k32,
// upper-triangular block tiles only (S = Z Z^T symmetric).
// Tile (I,J), J>I: exp-row-sums -> rows of block I, exp-col-sums -> block J.
// loss_i = (1 - pos_i)/tau + log( sum_{j != i} exp((dot_ij - 1)/tau) )
// 296 CTAs, 2 CTAs/SM; final logsumexp fused via completion ticket.
// (R8 showed legacy s8 IMMA runs at HALF the e4m3 rate on sm_103 — fp8 it is.)
// ---------------------------------------------------------------------------

#define NN      8192
#define DD      512
#define BHALF   4096
#define NCHUNK  4            // 512 fp8 bytes / 128-byte chunk
#define NTILES  2080
#define NCTAS   296

#define K1F     20.60992915555662f        // log2(e)/0.07
#define EXSC    0.08050753576389304f      // K1F / 256   (fp8 scale^2)
#define PSC     0.00390625f               // 1/256
#define INV_TAU 14.285714285714286f

#define A_BYTES  65536       // 128 rows x 512 B (4 chunks x 16 KB)
#define B_OFF    65536
#define B_BYTES  16384       // one B chunk: 128 rows x 128 B
#define SMEM_BYTES (A_BYTES + 2*B_BYTES + 1024)

__device__ __align__(128) unsigned char g_z[(size_t)NN * DD];   // e4m3, x16
__device__ float g_rowsum[NN];
__device__ float g_pos[NN];
__device__ unsigned g_done;

// ------------------------------- helpers -----------------------------------
__device__ __forceinline__ unsigned smem_u32(const void* p) {
    unsigned a;
    asm("{ .reg .u64 t; cvta.to.shared.u64 t, %1; cvt.u32.u64 %0, t; }"
        : "=r"(a) : "l"(p));
    return a;
}
__device__ __forceinline__ unsigned swz(unsigned off) {
    return off ^ ((off >> 3) & 0x70);
}
__device__ __forceinline__ void cp16(unsigned dst, const void* src) {
    asm volatile("cp.async.cg.shared.global [%0], [%1], 16;"
                 :: "r"(dst), "l"(src) : "memory");
}
#define CP_COMMIT() asm volatile("cp.async.commit_group;" ::: "memory")
#define CP_WAIT(n)  asm volatile("cp.async.wait_group %0;" :: "n"(n) : "memory")

__device__ __forceinline__ void ldsm_x4(unsigned* r, unsigned addr) {
    asm volatile("ldmatrix.sync.aligned.m8n8.x4.shared.b16 {%0,%1,%2,%3}, [%4];"
                 : "=r"(r[0]), "=r"(r[1]), "=r"(r[2]), "=r"(r[3]) : "r"(addr));
}
__device__ __forceinline__ void mma_fp8(float* c, const unsigned* a,
                                        unsigned b0, unsigned b1) {
    asm volatile(
        "mma.sync.aligned.m16n8k32.row.col.f32.e4m3.e4m3.f32 "
        "{%0,%1,%2,%3}, {%4,%5,%6,%7}, {%8,%9}, {%0,%1,%2,%3};"
        : "+f"(c[0]), "+f"(c[1]), "+f"(c[2]), "+f"(c[3])
        : "r"(a[0]), "r"(a[1]), "r"(a[2]), "r"(a[3]), "r"(b0), "r"(b1));
}
__device__ __forceinline__ float ex2s(float v) {   // exp((v/256 - 1)/tau)
    float y;
    asm("ex2.approx.ftz.f32 %0, %1;" : "=f"(y) : "f"(fmaf(v, EXSC, -K1F)));
    return y;
}
__device__ __forceinline__ unsigned short cvt2_e4m3(float lo, float hi) {
    unsigned short r;
    asm("cvt.rn.satfinite.e4m3x2.f32 %0, %1, %2;" : "=h"(r) : "f"(hi), "f"(lo));
    return r;
}

// decode flattened tile index -> (I, J)
__device__ __forceinline__ void tile_decode(int t, int& I, int& J) {
    int p = t / 65;
    int l = t - p * 65;
    int n1 = 64 - p;
    if (l < n1) { I = p;      J = p + l; }
    else        { I = 63 - p; J = I + (l - n1); }
}

// ------------------------- kernel 1: normalize -> fp8 ----------------------
__global__ __launch_bounds__(256) void ntx_normalize(const float* __restrict__ anchor,
                                                     const float* __restrict__ positive) {
    int gt = blockIdx.x * 256 + threadIdx.x;
    if (gt < NN) g_rowsum[gt] = 0.f;          // graph-replay safe re-init
    if (gt == 0) g_done = 0u;

    int row  = blockIdx.x * 8 + (threadIdx.x >> 5);
    int lane = threadIdx.x & 31;
    const float* src = (row < BHALF) ? (anchor + (size_t)row * DD)
                                     : (positive + (size_t)(row - BHALF) * DD);
    const float4* s4 = (const float4*)src;
    float4 v[4];
    float ss = 0.f;
#pragma unroll
    for (int q = 0; q < 4; q++) {
        v[q] = s4[lane + 32 * q];
        ss += v[q].x * v[q].x + v[q].y * v[q].y + v[q].z * v[q].z + v[q].w * v[q].w;
    }
#pragma unroll
    for (int o = 16; o > 0; o >>= 1) ss += __shfl_xor_sync(0xFFFFFFFFu, ss, o);
    float s16 = 16.0f / fmaxf(sqrtf(ss), 1e-8f);   // unit-norm then x16 for e4m3

    unsigned* zp = (unsigned*)(g_z + (size_t)row * DD);
#pragma unroll
    for (int q = 0; q < 4; q++) {
        unsigned lo = cvt2_e4m3(v[q].x * s16, v[q].y * s16);
        unsigned hi = cvt2_e4m3(v[q].z * s16, v[q].w * s16);
        zp[lane + 32 * q] = lo | (hi << 16);
    }
}

// ------------------------- kernel 2: upper-tri GEMM + exp-reduce -----------
__device__ __forceinline__ void issueB(unsigned bbase, int colbase, int k, int tid) {
#pragma unroll
    for (int it = 0; it < 4; it++) {
        int idx = tid + it * 256;
        int r = idx >> 3, c8 = idx & 7;
        const void* src = g_z + ((size_t)(colbase + r) << 9) + k * 128 + c8 * 16;
        cp16(bbase + swz((unsigned)(r * 128 + c8 * 16)), src);
    }
}

// ring depth 2: slot = m & 1
__device__ __forceinline__ void issue_chunk(unsigned Bb, int t0, int t1, int m, int tid) {
    int tt = t0 + (m >> 2);
    if (tt < t1) {
        int I2, J2;
        tile_decode(tt, I2, J2);
        issueB(Bb + (unsigned)(m & 1) * B_BYTES, J2 << 7, m & 3, tid);
    }
    CP_COMMIT();
}

__global__ __launch_bounds__(256, 2) void ntx_main(float* __restrict__ out) {
    extern __shared__ char smem_raw[];
    unsigned raw  = smem_u32(smem_raw);
    unsigned base = (raw + 1023u) & ~1023u;
    char* sp      = smem_raw + (base - raw);
    unsigned A  = base;
    unsigned Bb = base + B_OFF;

    int tid  = threadIdx.x;
    int wid  = tid >> 5, lane = tid & 31;
    int warpM = wid & 3, warpN = wid >> 2;     // 4 x 2 warp grid, tile 32x64
    int qrow = lane >> 2;

    int c  = blockIdx.x;
    int t0 = (c * NTILES) / NCTAS;
    int t1 = ((c + 1) * NTILES) / NCTAS;

    int sel = lane >> 3, lr = lane & 7;
    unsigned aoff[2][4];
#pragma unroll
    for (int mf = 0; mf < 2; mf++)
#pragma unroll
        for (int ks = 0; ks < 4; ks++) {
            int r = warpM * 32 + mf * 16 + ((sel & 1) << 3) + lr;
            unsigned cb = (unsigned)(ks * 32 + ((sel >> 1) << 4));
            aoff[mf][ks] = (unsigned)(r * 128) + (cb ^ ((unsigned)lr << 4));
        }
    unsigned boff[4][4];
#pragma unroll
    for (int p = 0; p < 4; p++)
#pragma unroll
        for (int ks = 0; ks < 4; ks++) {
            int r = warpN * 64 + p * 16 + ((sel & 1) << 3) + lr;
            unsigned cb = (unsigned)(ks * 32 + ((sel >> 1) << 4));
            boff[p][ks] = (unsigned)(r * 128) + (cb ^ ((unsigned)lr << 4));
        }

    issue_chunk(Bb, t0, t1, 0, tid);

    float acc[2][8][4];
    float rsum[2][2] = {{0.f, 0.f}, {0.f, 0.f}};
    int curI = -1;
    int cm = 0;

    for (int t = t0; t < t1; t++) {
        int I, J;
        tile_decode(t, I, J);
        int rowbase = I << 7, colbase = J << 7;

        if (I != curI) {
            if (curI >= 0) {
#pragma unroll
                for (int mf = 0; mf < 2; mf++)
#pragma unroll
                    for (int h = 0; h < 2; h++) {
                        float v = rsum[mf][h];
                        v += __shfl_xor_sync(0xFFFFFFFFu, v, 1);
                        v += __shfl_xor_sync(0xFFFFFFFFu, v, 2);
                        if ((lane & 3) == 0)
                            atomicAdd(&g_rowsum[(curI << 7) + warpM * 32 + mf * 16 + h * 8 + qrow], v);
                        rsum[mf][h] = 0.f;
                    }
            }
            __syncthreads();                   // all readers of old A done
#pragma unroll
            for (int it = 0; it < 16; it++) {
                int x = tid + it * 256;
                int r = x >> 5, u = x & 31, ck = u >> 3, c8 = u & 7;
                const uint4* src = (const uint4*)(g_z + ((size_t)(rowbase + r) << 9)
                                                  + ck * 128 + c8 * 16);
                *(uint4*)(sp + ck * 16384 + swz((unsigned)(r * 128 + c8 * 16))) = *src;
            }
            __syncthreads();
            curI = I;
        }

#pragma unroll
        for (int mf = 0; mf < 2; mf++)
#pragma unroll
            for (int nf = 0; nf < 8; nf++)
#pragma unroll
                for (int e = 0; e < 4; e++) acc[mf][nf][e] = 0.f;

#pragma unroll
        for (int k = 0; k < NCHUNK; k++) {
            CP_WAIT(0);
            __syncthreads();
            issue_chunk(Bb, t0, t1, cm + 1, tid);

            unsigned Ac = A + k * 16384;
            unsigned Bc = Bb + (unsigned)(cm & 1) * B_BYTES;
#pragma unroll
            for (int ks = 0; ks < 4; ks++) {
                unsigned afr[2][4];
                ldsm_x4(afr[0], Ac + aoff[0][ks]);
                ldsm_x4(afr[1], Ac + aoff[1][ks]);
                unsigned bfr[4][4];
#pragma unroll
                for (int p = 0; p < 4; p++) ldsm_x4(bfr[p], Bc + boff[p][ks]);
#pragma unroll
                for (int mf = 0; mf < 2; mf++)
#pragma unroll
                    for (int nf = 0; nf < 8; nf++)
                        mma_fp8(acc[mf][nf], afr[mf],
                                bfr[nf >> 1][nf & 1],
                                bfr[nf >> 1][2 + (nf & 1)]);
            }
            cm++;
        }

        // ---- epilogue ----
        bool isdiag = (J == I);
        bool ispos  = (J == I + 32);

        if (isdiag | ispos) {
#pragma unroll
            for (int mf = 0; mf < 2; mf++)
#pragma unroll
                for (int h = 0; h < 2; h++) {
                    int rloc = warpM * 32 + mf * 16 + h * 8 + qrow;
                    int cc = rloc - warpN * 64;
                    if (cc >= 0 && cc < 64 && (((cc >> 1) & 3) == (lane & 3))) {
                        float v = acc[mf][cc >> 3][(h << 1) | (cc & 1)];
                        if (isdiag) rsum[mf][h] -= ex2s(v);
                        if (ispos) {
                            g_pos[rowbase + rloc] = v * PSC;
                            g_pos[rowbase + rloc + BHALF] = v * PSC;
                        }
                    }
                }
        }

        float colp[16];
#pragma unroll
        for (int q = 0; q < 16; q++) colp[q] = 0.f;
#pragma unroll
        for (int mf = 0; mf < 2; mf++) {
            float slo = 0.f, shi = 0.f;
#pragma unroll
            for (int nf = 0; nf < 8; nf++) {
                float e0 = ex2s(acc[mf][nf][0]);
                float e1 = ex2s(acc[mf][nf][1]);
                float e2 = ex2s(acc[mf][nf][2]);
                float e3 = ex2s(acc[mf][nf][3]);
                slo += e0 + e1;
                shi += e2 + e3;
                colp[nf * 2]     += e0 + e2;
                colp[nf * 2 + 1] += e1 + e3;
            }
            rsum[mf][0] += slo;
            rsum[mf][1] += shi;
        }

        if (!isdiag) {
#pragma unroll
            for (int q = 0; q < 16; q++) {
                float v = colp[q];
                v += __shfl_xor_sync(0xFFFFFFFFu, v, 4);
                v += __shfl_xor_sync(0xFFFFFFFFu, v, 8);
                v += __shfl_xor_sync(0xFFFFFFFFu, v, 16);
                if (lane < 4) {
                    int ccol = (q >> 1) * 8 + 2 * lane + (q & 1);
                    atomicAdd(&g_rowsum[colbase + warpN * 64 + ccol], v);
                }
            }
        }
    }

    // final row flush
#pragma unroll
    for (int mf = 0; mf < 2; mf++)
#pragma unroll
        for (int h = 0; h < 2; h++) {
            float v = rsum[mf][h];
            v += __shfl_xor_sync(0xFFFFFFFFu, v, 1);
            v += __shfl_xor_sync(0xFFFFFFFFu, v, 2);
            if ((lane & 3) == 0 && curI >= 0)
                atomicAdd(&g_rowsum[(curI << 7) + warpM * 32 + mf * 16 + h * 8 + qrow], v);
        }

    // ---- completion ticket: last CTA computes the loss ----
    __threadfence();
    __syncthreads();
    __shared__ unsigned ticket;
    if (tid == 0) ticket = atomicAdd(&g_done, 1u);
    __syncthreads();
    if (ticket == NCTAS - 1) {
        float local = 0.f;
        for (int r = tid; r < NN; r += 256)
            local += (1.0f - g_pos[r]) * INV_TAU + __logf(g_rowsum[r]);
#pragma unroll
        for (int o = 16; o > 0; o >>= 1) local += __shfl_xor_sync(0xFFFFFFFFu, local, o);
        __shared__ float red[8];
        if (lane == 0) red[wid] = local;
        __syncthreads();
        if (tid < 8) {
            float v = red[tid];
#pragma unroll
            for (int o = 4; o > 0; o >>= 1) v += __shfl_xor_sync(0xFFu, v, o);
            if (tid == 0) out[0] = v * (1.0f / (float)NN);
        }
    }
}

// ---------------------------------------------------------------------------
extern "C" void kernel_launch(void* const* d_in, const int* in_sizes, int n_in,
                              void* d_out, int out_size) {
    (void)in_sizes; (void)n_in; (void)out_size;
    const float* anchor   = (const float*)d_in[0];
    const float* positive = (const float*)d_in[1];

    cudaFuncSetAttribute(ntx_main, cudaFuncAttributeMaxDynamicSharedMemorySize,
                         SMEM_BYTES);

    ntx_normalize<<<NN / 8, 256>>>(anchor, positive);
    ntx_main<<<NCTAS, 256, SMEM_BYTES>>>((float*)d_out);
}

// round 10
// speedup vs baseline: 2.4393x; 1.3734x over previous
#include <cuda_runtime.h>
#include <cuda_bf16.h>
#include <cuda_fp16.h>

// ---------------------------------------------------------------------------
// NT-Xent loss, N=8192, D=512. FP8 (e4m3, scale 16) mma.sync m16n8k32 with
// F16 ACCUMULATION (2x rate vs f32-acc on legacy fp8 paths), upper-triangular
// block tiles only (S = Z Z^T symmetric).
// Tile (I,J), J>I: exp-row-sums -> rows of block I, exp-col-sums -> block J.
// loss_i = (1 - pos_i)/tau + log( sum_{j != i} exp((dot_ij - 1)/tau) )
// 296 CTAs, 2 CTAs/SM; final logsumexp fused via completion ticket.
// ---------------------------------------------------------------------------

#define NN      8192
#define DD      512
#define BHALF   4096
#define NCHUNK  4            // 512 fp8 bytes / 128-byte chunk
#define NTILES  2080
#define NCTAS   296

#define K1F     20.60992915555662f        // log2(e)/0.07
#define EXSC    0.08050753576389304f      // K1F / 256   (fp8 scale^2)
#define PSC     0.00390625f               // 1/256
#define INV_TAU 14.285714285714286f

#define A_BYTES  65536       // 128 rows x 512 B (4 chunks x 16 KB)
#define B_OFF    65536
#define B_BYTES  16384       // one B chunk: 128 rows x 128 B
#define SMEM_BYTES (A_BYTES + 2*B_BYTES + 1024)

__device__ __align__(128) unsigned char g_z[(size_t)NN * DD];   // e4m3, x16
__device__ float g_rowsum[NN];
__device__ float g_pos[NN];
__device__ unsigned g_done;

// ------------------------------- helpers -----------------------------------
__device__ __forceinline__ unsigned smem_u32(const void* p) {
    unsigned a;
    asm("{ .reg .u64 t; cvta.to.shared.u64 t, %1; cvt.u32.u64 %0, t; }"
        : "=r"(a) : "l"(p));
    return a;
}
__device__ __forceinline__ unsigned swz(unsigned off) {
    return off ^ ((off >> 3) & 0x70);
}
__device__ __forceinline__ void cp16(unsigned dst, const void* src) {
    asm volatile("cp.async.cg.shared.global [%0], [%1], 16;"
                 :: "r"(dst), "l"(src) : "memory");
}
#define CP_COMMIT() asm volatile("cp.async.commit_group;" ::: "memory")
#define CP_WAIT(n)  asm volatile("cp.async.wait_group %0;" :: "n"(n) : "memory")

__device__ __forceinline__ void ldsm_x4(unsigned* r, unsigned addr) {
    asm volatile("ldmatrix.sync.aligned.m8n8.x4.shared.b16 {%0,%1,%2,%3}, [%4];"
                 : "=r"(r[0]), "=r"(r[1]), "=r"(r[2]), "=r"(r[3]) : "r"(addr));
}
// fp8 mma, f16 accumulator: acc = 2 x b32 regs, each holding half2
// reg0 = (c0, c1) row qrow; reg1 = (c2, c3) row qrow+8
__device__ __forceinline__ void mma_fp8h(unsigned* c, const unsigned* a,
                                         unsigned b0, unsigned b1) {
    asm volatile(
        "mma.sync.aligned.m16n8k32.row.col.f16.e4m3.e4m3.f16 "
        "{%0,%1}, {%2,%3,%4,%5}, {%6,%7}, {%0,%1};"
        : "+r"(c[0]), "+r"(c[1])
        : "r"(a[0]), "r"(a[1]), "r"(a[2]), "r"(a[3]), "r"(b0), "r"(b1));
}
__device__ __forceinline__ float ex2s(float v) {   // exp((v/256 - 1)/tau)
    float y;
    asm("ex2.approx.ftz.f32 %0, %1;" : "=f"(y) : "f"(fmaf(v, EXSC, -K1F)));
    return y;
}
__device__ __forceinline__ unsigned short cvt2_e4m3(float lo, float hi) {
    unsigned short r;
    asm("cvt.rn.satfinite.e4m3x2.f32 %0, %1, %2;" : "=h"(r) : "f"(hi), "f"(lo));
    return r;
}

// decode flattened tile index -> (I, J)
__device__ __forceinline__ void tile_decode(int t, int& I, int& J) {
    int p = t / 65;
    int l = t - p * 65;
    int n1 = 64 - p;
    if (l < n1) { I = p;      J = p + l; }
    else        { I = 63 - p; J = I + (l - n1); }
}

// ------------------------- kernel 1: normalize -> fp8 ----------------------
__global__ __launch_bounds__(256) void ntx_normalize(const float* __restrict__ anchor,
                                                     const float* __restrict__ positive) {
    int gt = blockIdx.x * 256 + threadIdx.x;
    if (gt < NN) g_rowsum[gt] = 0.f;          // graph-replay safe re-init
    if (gt == 0) g_done = 0u;

    int row  = blockIdx.x * 8 + (threadIdx.x >> 5);
    int lane = threadIdx.x & 31;
    const float* src = (row < BHALF) ? (anchor + (size_t)row * DD)
                                     : (positive + (size_t)(row - BHALF) * DD);
    const float4* s4 = (const float4*)src;
    float4 v[4];
    float ss = 0.f;
#pragma unroll
    for (int q = 0; q < 4; q++) {
        v[q] = s4[lane + 32 * q];
        ss += v[q].x * v[q].x + v[q].y * v[q].y + v[q].z * v[q].z + v[q].w * v[q].w;
    }
#pragma unroll
    for (int o = 16; o > 0; o >>= 1) ss += __shfl_xor_sync(0xFFFFFFFFu, ss, o);
    float s16 = 16.0f / fmaxf(sqrtf(ss), 1e-8f);   // unit-norm then x16 for e4m3

    unsigned* zp = (unsigned*)(g_z + (size_t)row * DD);
#pragma unroll
    for (int q = 0; q < 4; q++) {
        unsigned lo = cvt2_e4m3(v[q].x * s16, v[q].y * s16);
        unsigned hi = cvt2_e4m3(v[q].z * s16, v[q].w * s16);
        zp[lane + 32 * q] = lo | (hi << 16);
    }
}

// ------------------------- kernel 2: upper-tri GEMM + exp-reduce -----------
__device__ __forceinline__ void issueB(unsigned bbase, int colbase, int k, int tid) {
#pragma unroll
    for (int it = 0; it < 4; it++) {
        int idx = tid + it * 256;
        int r = idx >> 3, c8 = idx & 7;
        const void* src = g_z + ((size_t)(colbase + r) << 9) + k * 128 + c8 * 16;
        cp16(bbase + swz((unsigned)(r * 128 + c8 * 16)), src);
    }
}

// ring depth 2: slot = m & 1
__device__ __forceinline__ void issue_chunk(unsigned Bb, int t0, int t1, int m, int tid) {
    int tt = t0 + (m >> 2);
    if (tt < t1) {
        int I2, J2;
        tile_decode(tt, I2, J2);
        issueB(Bb + (unsigned)(m & 1) * B_BYTES, J2 << 7, m & 3, tid);
    }
    CP_COMMIT();
}

__global__ __launch_bounds__(256, 2) void ntx_main(float* __restrict__ out) {
    extern __shared__ char smem_raw[];
    unsigned raw  = smem_u32(smem_raw);
    unsigned base = (raw + 1023u) & ~1023u;
    char* sp      = smem_raw + (base - raw);
    unsigned A  = base;
    unsigned Bb = base + B_OFF;

    int tid  = threadIdx.x;
    int wid  = tid >> 5, lane = tid & 31;
    int warpM = wid & 3, warpN = wid >> 2;     // 4 x 2 warp grid, tile 32x64
    int qrow = lane >> 2;

    int c  = blockIdx.x;
    int t0 = (c * NTILES) / NCTAS;
    int t1 = ((c + 1) * NTILES) / NCTAS;

    int sel = lane >> 3, lr = lane & 7;
    unsigned aoff[2][4];
#pragma unroll
    for (int mf = 0; mf < 2; mf++)
#pragma unroll
        for (int ks = 0; ks < 4; ks++) {
            int r = warpM * 32 + mf * 16 + ((sel & 1) << 3) + lr;
            unsigned cb = (unsigned)(ks * 32 + ((sel >> 1) << 4));
            aoff[mf][ks] = (unsigned)(r * 128) + (cb ^ ((unsigned)lr << 4));
        }
    unsigned boff[4][4];
#pragma unroll
    for (int p = 0; p < 4; p++)
#pragma unroll
        for (int ks = 0; ks < 4; ks++) {
            int r = warpN * 64 + p * 16 + ((sel & 1) << 3) + lr;
            unsigned cb = (unsigned)(ks * 32 + ((sel >> 1) << 4));
            boff[p][ks] = (unsigned)(r * 128) + (cb ^ ((unsigned)lr << 4));
        }

    issue_chunk(Bb, t0, t1, 0, tid);

    unsigned acc[2][8][2];                     // f16x2 accumulators
    float rsum[2][2] = {{0.f, 0.f}, {0.f, 0.f}};
    int curI = -1;
    int cm = 0;

    for (int t = t0; t < t1; t++) {
        int I, J;
        tile_decode(t, I, J);
        int rowbase = I << 7, colbase = J << 7;

        if (I != curI) {
            if (curI >= 0) {
#pragma unroll
                for (int mf = 0; mf < 2; mf++)
#pragma unroll
                    for (int h = 0; h < 2; h++) {
                        float v = rsum[mf][h];
                        v += __shfl_xor_sync(0xFFFFFFFFu, v, 1);
                        v += __shfl_xor_sync(0xFFFFFFFFu, v, 2);
                        if ((lane & 3) == 0)
                            atomicAdd(&g_rowsum[(curI << 7) + warpM * 32 + mf * 16 + h * 8 + qrow], v);
                        rsum[mf][h] = 0.f;
                    }
            }
            __syncthreads();                   // all readers of old A done
#pragma unroll
            for (int it = 0; it < 16; it++) {
                int x = tid + it * 256;
                int r = x >> 5, u = x & 31, ck = u >> 3, c8 = u & 7;
                const uint4* src = (const uint4*)(g_z + ((size_t)(rowbase + r) << 9)
                                                  + ck * 128 + c8 * 16);
                *(uint4*)(sp + ck * 16384 + swz((unsigned)(r * 128 + c8 * 16))) = *src;
            }
            __syncthreads();
            curI = I;
        }

#pragma unroll
        for (int mf = 0; mf < 2; mf++)
#pragma unroll
            for (int nf = 0; nf < 8; nf++) {
                acc[mf][nf][0] = 0u;
                acc[mf][nf][1] = 0u;
            }

#pragma unroll
        for (int k = 0; k < NCHUNK; k++) {
            CP_WAIT(0);
            __syncthreads();
            issue_chunk(Bb, t0, t1, cm + 1, tid);

            unsigned Ac = A + k * 16384;
            unsigned Bc = Bb + (unsigned)(cm & 1) * B_BYTES;
#pragma unroll
            for (int ks = 0; ks < 4; ks++) {
                unsigned afr[2][4];
                ldsm_x4(afr[0], Ac + aoff[0][ks]);
                ldsm_x4(afr[1], Ac + aoff[1][ks]);
                unsigned bfr[4][4];
#pragma unroll
                for (int p = 0; p < 4; p++) ldsm_x4(bfr[p], Bc + boff[p][ks]);
#pragma unroll
                for (int mf = 0; mf < 2; mf++)
#pragma unroll
                    for (int nf = 0; nf < 8; nf++)
                        mma_fp8h(acc[mf][nf], afr[mf],
                                 bfr[nf >> 1][nf & 1],
                                 bfr[nf >> 1][2 + (nf & 1)]);
            }
            cm++;
        }

        // ---- epilogue ----
        bool isdiag = (J == I);
        bool ispos  = (J == I + 32);

        if (isdiag | ispos) {
#pragma unroll
            for (int mf = 0; mf < 2; mf++)
#pragma unroll
                for (int h = 0; h < 2; h++) {
                    int rloc = warpM * 32 + mf * 16 + h * 8 + qrow;
                    int cc = rloc - warpN * 64;
                    if (cc >= 0 && cc < 64 && (((cc >> 1) & 3) == (lane & 3))) {
                        __half2 hp = *(__half2*)&acc[mf][cc >> 3][h];
                        float v = (cc & 1) ? __high2float(hp) : __low2float(hp);
                        if (isdiag) rsum[mf][h] -= ex2s(v);
                        if (ispos) {
                            g_pos[rowbase + rloc] = v * PSC;
                            g_pos[rowbase + rloc + BHALF] = v * PSC;
                        }
                    }
                }
        }

        float colp[16];
#pragma unroll
        for (int q = 0; q < 16; q++) colp[q] = 0.f;
#pragma unroll
        for (int mf = 0; mf < 2; mf++) {
            float slo = 0.f, shi = 0.f;
#pragma unroll
            for (int nf = 0; nf < 8; nf++) {
                float2 f01 = __half22float2(*(__half2*)&acc[mf][nf][0]);
                float2 f23 = __half22float2(*(__half2*)&acc[mf][nf][1]);
                float e0 = ex2s(f01.x);
                float e1 = ex2s(f01.y);
                float e2 = ex2s(f23.x);
                float e3 = ex2s(f23.y);
                slo += e0 + e1;
                shi += e2 + e3;
                colp[nf * 2]     += e0 + e2;
                colp[nf * 2 + 1] += e1 + e3;
            }
            rsum[mf][0] += slo;
            rsum[mf][1] += shi;
        }

        if (!isdiag) {
#pragma unroll
            for (int q = 0; q < 16; q++) {
                float v = colp[q];
                v += __shfl_xor_sync(0xFFFFFFFFu, v, 4);
                v += __shfl_xor_sync(0xFFFFFFFFu, v, 8);
                v += __shfl_xor_sync(0xFFFFFFFFu, v, 16);
                if (lane < 4) {
                    int ccol = (q >> 1) * 8 + 2 * lane + (q & 1);
                    atomicAdd(&g_rowsum[colbase + warpN * 64 + ccol], v);
                }
            }
        }
    }

    // final row flush
#pragma unroll
    for (int mf = 0; mf < 2; mf++)
#pragma unroll
        for (int h = 0; h < 2; h++) {
            float v = rsum[mf][h];
            v += __shfl_xor_sync(0xFFFFFFFFu, v, 1);
            v += __shfl_xor_sync(0xFFFFFFFFu, v, 2);
            if ((lane & 3) == 0 && curI >= 0)
                atomicAdd(&g_rowsum[(curI << 7) + warpM * 32 + mf * 16 + h * 8 + qrow], v);
        }

    // ---- completion ticket: last CTA computes the loss ----
    __threadfence();
    __syncthreads();
    __shared__ unsigned ticket;
    if (tid == 0) ticket = atomicAdd(&g_done, 1u);
    __syncthreads();
    if (ticket == NCTAS - 1) {
        float local = 0.f;
        for (int r = tid; r < NN; r += 256)
            local += (1.0f - g_pos[r]) * INV_TAU + __logf(g_rowsum[r]);
#pragma unroll
        for (int o = 16; o > 0; o >>= 1) local += __shfl_xor_sync(0xFFFFFFFFu, local, o);
        __shared__ float red[8];
        if (lane == 0) red[wid] = local;
        __syncthreads();
        if (tid < 8) {
            float v = red[tid];
#pragma unroll
            for (int o = 4; o > 0; o >>= 1) v += __shfl_xor_sync(0xFFu, v, o);
            if (tid == 0) out[0] = v * (1.0f / (float)NN);
        }
    }
}

// ---------------------------------------------------------------------------
extern "C" void kernel_launch(void* const* d_in, const int* in_sizes, int n_in,
                              void* d_out, int out_size) {
    (void)in_sizes; (void)n_in; (void)out_size;
    const float* anchor   = (const float*)d_in[0];
    const float* positive = (const float*)d_in[1];

    cudaFuncSetAttribute(ntx_main, cudaFuncAttributeMaxDynamicSharedMemorySize,
                         SMEM_BYTES);

    ntx_normalize<<<NN / 8, 256>>>(anchor, positive);
    ntx_main<<<NCTAS, 256, SMEM_BYTES>>>((float*)d_out);
}

// round 11
// speedup vs baseline: 2.7015x; 1.1075x over previous
#include <cuda_runtime.h>
#include <cuda_bf16.h>
#include <cuda_fp16.h>

// ---------------------------------------------------------------------------
// NT-Xent loss, N=8192, D=512. FP8 (e4m3, scale 16) mma.sync m16n8k32 with
// f16 accumulation (2x rate), upper-triangular tiles (S = Z Z^T symmetric).
// Tile (I,J), J>I: exp-row-sums -> rows of block I, exp-col-sums -> block J.
// loss_i = (1 - pos_i)/tau + log( sum_{j != i} exp((dot_ij - 1)/tau) )
// 296 CTAs of 512 threads, 2 CTAs/SM (32 warps/SM) to hide mma/ldsm latency.
// Warp grid 4x4, warp tile 32x32. Final logsumexp fused via completion ticket.
// ---------------------------------------------------------------------------

#define NN      8192
#define DD      512
#define BHALF   4096
#define NCHUNK  4            // 512 fp8 bytes / 128-byte chunk
#define NTILES  2080
#define NCTAS   296
#define NTHR    512

#define K1F     20.60992915555662f        // log2(e)/0.07
#define EXSC    0.08050753576389304f      // K1F / 256   (fp8 scale^2)
#define PSC     0.00390625f               // 1/256
#define INV_TAU 14.285714285714286f

#define A_BYTES  65536       // 128 rows x 512 B (4 chunks x 16 KB)
#define B_OFF    65536
#define B_BYTES  16384       // one B chunk: 128 rows x 128 B
#define SMEM_BYTES (A_BYTES + 2*B_BYTES + 1024)

__device__ __align__(128) unsigned char g_z[(size_t)NN * DD];   // e4m3, x16
__device__ float g_rowsum[NN];
__device__ float g_pos[NN];
__device__ unsigned g_done;

// ------------------------------- helpers -----------------------------------
__device__ __forceinline__ unsigned smem_u32(const void* p) {
    unsigned a;
    asm("{ .reg .u64 t; cvta.to.shared.u64 t, %1; cvt.u32.u64 %0, t; }"
        : "=r"(a) : "l"(p));
    return a;
}
__device__ __forceinline__ unsigned swz(unsigned off) {
    return off ^ ((off >> 3) & 0x70);
}
__device__ __forceinline__ void cp16(unsigned dst, const void* src) {
    asm volatile("cp.async.cg.shared.global [%0], [%1], 16;"
                 :: "r"(dst), "l"(src) : "memory");
}
#define CP_COMMIT() asm volatile("cp.async.commit_group;" ::: "memory")
#define CP_WAIT(n)  asm volatile("cp.async.wait_group %0;" :: "n"(n) : "memory")

__device__ __forceinline__ void ldsm_x4(unsigned* r, unsigned addr) {
    asm volatile("ldmatrix.sync.aligned.m8n8.x4.shared.b16 {%0,%1,%2,%3}, [%4];"
                 : "=r"(r[0]), "=r"(r[1]), "=r"(r[2]), "=r"(r[3]) : "r"(addr));
}
// fp8 mma, f16 accumulator (c0: rows lane>>2, c1: +8; cols 2*(lane&3)+{0,1})
__device__ __forceinline__ void mma_fp8h(unsigned* c, const unsigned* a,
                                         unsigned b0, unsigned b1) {
    asm volatile(
        "mma.sync.aligned.m16n8k32.row.col.f16.e4m3.e4m3.f16 "
        "{%0,%1}, {%2,%3,%4,%5}, {%6,%7}, {%0,%1};"
        : "+r"(c[0]), "+r"(c[1])
        : "r"(a[0]), "r"(a[1]), "r"(a[2]), "r"(a[3]), "r"(b0), "r"(b1));
}
__device__ __forceinline__ float ex2s(float v) {   // exp((v/256 - 1)/tau)
    float y;
    asm("ex2.approx.ftz.f32 %0, %1;" : "=f"(y) : "f"(fmaf(v, EXSC, -K1F)));
    return y;
}
__device__ __forceinline__ unsigned short cvt2_e4m3(float lo, float hi) {
    unsigned short r;
    asm("cvt.rn.satfinite.e4m3x2.f32 %0, %1, %2;" : "=h"(r) : "f"(hi), "f"(lo));
    return r;
}

// decode flattened tile index -> (I, J)
__device__ __forceinline__ void tile_decode(int t, int& I, int& J) {
    int p = t / 65;
    int l = t - p * 65;
    int n1 = 64 - p;
    if (l < n1) { I = p;      J = p + l; }
    else        { I = 63 - p; J = I + (l - n1); }
}

// ------------------------- kernel 1: normalize -> fp8 ----------------------
__global__ __launch_bounds__(256) void ntx_normalize(const float* __restrict__ anchor,
                                                     const float* __restrict__ positive) {
    int gt = blockIdx.x * 256 + threadIdx.x;
    if (gt < NN) g_rowsum[gt] = 0.f;          // graph-replay safe re-init
    if (gt == 0) g_done = 0u;

    int row  = blockIdx.x * 8 + (threadIdx.x >> 5);
    int lane = threadIdx.x & 31;
    const float* src = (row < BHALF) ? (anchor + (size_t)row * DD)
                                     : (positive + (size_t)(row - BHALF) * DD);
    const float4* s4 = (const float4*)src;
    float4 v[4];
    float ss = 0.f;
#pragma unroll
    for (int q = 0; q < 4; q++) {
        v[q] = s4[lane + 32 * q];
        ss += v[q].x * v[q].x + v[q].y * v[q].y + v[q].z * v[q].z + v[q].w * v[q].w;
    }
#pragma unroll
    for (int o = 16; o > 0; o >>= 1) ss += __shfl_xor_sync(0xFFFFFFFFu, ss, o);
    float s16 = 16.0f / fmaxf(sqrtf(ss), 1e-8f);

    unsigned* zp = (unsigned*)(g_z + (size_t)row * DD);
#pragma unroll
    for (int q = 0; q < 4; q++) {
        unsigned lo = cvt2_e4m3(v[q].x * s16, v[q].y * s16);
        unsigned hi = cvt2_e4m3(v[q].z * s16, v[q].w * s16);
        zp[lane + 32 * q] = lo | (hi << 16);
    }
}

// ------------------------- kernel 2: upper-tri GEMM + exp-reduce -----------
__device__ __forceinline__ void issueB(unsigned bbase, int colbase, int k, int tid) {
#pragma unroll
    for (int it = 0; it < 2; it++) {
        int idx = tid + it * NTHR;
        int r = idx >> 3, c8 = idx & 7;
        const void* src = g_z + ((size_t)(colbase + r) << 9) + k * 128 + c8 * 16;
        cp16(bbase + swz((unsigned)(r * 128 + c8 * 16)), src);
    }
}

// ring depth 2: slot = m & 1
__device__ __forceinline__ void issue_chunk(unsigned Bb, int t0, int t1, int m, int tid) {
    int tt = t0 + (m >> 2);
    if (tt < t1) {
        int I2, J2;
        tile_decode(tt, I2, J2);
        issueB(Bb + (unsigned)(m & 1) * B_BYTES, J2 << 7, m & 3, tid);
    }
    CP_COMMIT();
}

__global__ __launch_bounds__(NTHR, 2) void ntx_main(float* __restrict__ out) {
    extern __shared__ char smem_raw[];
    unsigned raw  = smem_u32(smem_raw);
    unsigned base = (raw + 1023u) & ~1023u;
    char* sp      = smem_raw + (base - raw);
    unsigned A  = base;
    unsigned Bb = base + B_OFF;

    int tid  = threadIdx.x;
    int wid  = tid >> 5, lane = tid & 31;
    int warpM = wid & 3, warpN = wid >> 2;     // 4 x 4 warp grid, tile 32x32
    int qrow = lane >> 2;

    int c  = blockIdx.x;
    int t0 = (c * NTILES) / NCTAS;
    int t1 = ((c + 1) * NTILES) / NCTAS;

    // compact ldmatrix addressing: shared k-column xor table + row bases
    int sel = lane >> 3, lr = lane & 7;
    unsigned cbx[4];
#pragma unroll
    for (int ks = 0; ks < 4; ks++)
        cbx[ks] = ((unsigned)(ks * 32 + ((sel >> 1) << 4))) ^ ((unsigned)lr << 4);
    unsigned arowb[2];                         // A: rows warpM*32 + mf*16
#pragma unroll
    for (int mf = 0; mf < 2; mf++)
        arowb[mf] = (unsigned)((warpM * 32 + mf * 16 + ((sel & 1) << 3) + lr) * 128);
    unsigned browb[2];                         // B: rows warpN*32 + p*16
#pragma unroll
    for (int p = 0; p < 2; p++)
        browb[p] = (unsigned)((warpN * 32 + p * 16 + ((sel & 1) << 3) + lr) * 128);

    issue_chunk(Bb, t0, t1, 0, tid);

    unsigned acc[2][4][2];                     // f16x2 accumulators (32x32 tile)
    float rsum[2][2] = {{0.f, 0.f}, {0.f, 0.f}};
    int curI = -1;
    int cm = 0;

    for (int t = t0; t < t1; t++) {
        int I, J;
        tile_decode(t, I, J);
        int rowbase = I << 7, colbase = J << 7;

        if (I != curI) {
            if (curI >= 0) {
#pragma unroll
                for (int mf = 0; mf < 2; mf++)
#pragma unroll
                    for (int h = 0; h < 2; h++) {
                        float v = rsum[mf][h];
                        v += __shfl_xor_sync(0xFFFFFFFFu, v, 1);
                        v += __shfl_xor_sync(0xFFFFFFFFu, v, 2);
                        if ((lane & 3) == 0)
                            atomicAdd(&g_rowsum[(curI << 7) + warpM * 32 + mf * 16 + h * 8 + qrow], v);
                        rsum[mf][h] = 0.f;
                    }
            }
            __syncthreads();                   // all readers of old A done
#pragma unroll
            for (int it = 0; it < 8; it++) {
                int x = tid + it * NTHR;
                int r = x >> 5, u = x & 31, ck = u >> 3, c8 = u & 7;
                const uint4* src = (const uint4*)(g_z + ((size_t)(rowbase + r) << 9)
                                                  + ck * 128 + c8 * 16);
                *(uint4*)(sp + ck * 16384 + swz((unsigned)(r * 128 + c8 * 16))) = *src;
            }
            __syncthreads();
            curI = I;
        }

#pragma unroll
        for (int mf = 0; mf < 2; mf++)
#pragma unroll
            for (int nf = 0; nf < 4; nf++) {
                acc[mf][nf][0] = 0u;
                acc[mf][nf][1] = 0u;
            }

#pragma unroll
        for (int k = 0; k < NCHUNK; k++) {
            CP_WAIT(0);
            __syncthreads();
            issue_chunk(Bb, t0, t1, cm + 1, tid);

            unsigned Ac = A + k * 16384;
            unsigned Bc = Bb + (unsigned)(cm & 1) * B_BYTES;
#pragma unroll
            for (int ks = 0; ks < 4; ks++) {
                unsigned afr[2][4];
                ldsm_x4(afr[0], Ac + arowb[0] + cbx[ks]);
                ldsm_x4(afr[1], Ac + arowb[1] + cbx[ks]);
                unsigned bfr[2][4];
                ldsm_x4(bfr[0], Bc + browb[0] + cbx[ks]);
                ldsm_x4(bfr[1], Bc + browb[1] + cbx[ks]);
#pragma unroll
                for (int mf = 0; mf < 2; mf++)
#pragma unroll
                    for (int nf = 0; nf < 4; nf++)
                        mma_fp8h(acc[mf][nf], afr[mf],
                                 bfr[nf >> 1][nf & 1],
                                 bfr[nf >> 1][2 + (nf & 1)]);
            }
            cm++;
        }

        // ---- epilogue ----
        bool isdiag = (J == I);
        bool ispos  = (J == I + 32);

        if (isdiag | ispos) {
#pragma unroll
            for (int mf = 0; mf < 2; mf++)
#pragma unroll
                for (int h = 0; h < 2; h++) {
                    int rloc = warpM * 32 + mf * 16 + h * 8 + qrow;
                    int cc = rloc - warpN * 32;
                    if (cc >= 0 && cc < 32 && (((cc >> 1) & 3) == (lane & 3))) {
                        __half2 hp = *(__half2*)&acc[mf][cc >> 3][h];
                        float v = (cc & 1) ? __high2float(hp) : __low2float(hp);
                        if (isdiag) rsum[mf][h] -= ex2s(v);
                        if (ispos) {
                            g_pos[rowbase + rloc] = v * PSC;
                            g_pos[rowbase + rloc + BHALF] = v * PSC;
                        }
                    }
                }
        }

        float colp[8];
#pragma unroll
        for (int q = 0; q < 8; q++) colp[q] = 0.f;
#pragma unroll
        for (int mf = 0; mf < 2; mf++) {
            float slo = 0.f, shi = 0.f;
#pragma unroll
            for (int nf = 0; nf < 4; nf++) {
                float2 f01 = __half22float2(*(__half2*)&acc[mf][nf][0]);
                float2 f23 = __half22float2(*(__half2*)&acc[mf][nf][1]);
                float e0 = ex2s(f01.x);
                float e1 = ex2s(f01.y);
                float e2 = ex2s(f23.x);
                float e3 = ex2s(f23.y);
                slo += e0 + e1;
                shi += e2 + e3;
                colp[nf * 2]     += e0 + e2;
                colp[nf * 2 + 1] += e1 + e3;
            }
            rsum[mf][0] += slo;
            rsum[mf][1] += shi;
        }

        if (!isdiag) {
#pragma unroll
            for (int q = 0; q < 8; q++) {
                float v = colp[q];
                v += __shfl_xor_sync(0xFFFFFFFFu, v, 4);
                v += __shfl_xor_sync(0xFFFFFFFFu, v, 8);
                v += __shfl_xor_sync(0xFFFFFFFFu, v, 16);
                if (lane < 4) {
                    int ccol = (q >> 1) * 8 + 2 * lane + (q & 1);
                    atomicAdd(&g_rowsum[colbase + warpN * 32 + ccol], v);
                }
            }
        }
    }

    // final row flush
#pragma unroll
    for (int mf = 0; mf < 2; mf++)
#pragma unroll
        for (int h = 0; h < 2; h++) {
            float v = rsum[mf][h];
            v += __shfl_xor_sync(0xFFFFFFFFu, v, 1);
            v += __shfl_xor_sync(0xFFFFFFFFu, v, 2);
            if ((lane & 3) == 0 && curI >= 0)
                atomicAdd(&g_rowsum[(curI << 7) + warpM * 32 + mf * 16 + h * 8 + qrow], v);
        }

    // ---- completion ticket: last CTA computes the loss ----
    __threadfence();
    __syncthreads();
    __shared__ unsigned ticket;
    if (tid == 0) ticket = atomicAdd(&g_done, 1u);
    __syncthreads();
    if (ticket == NCTAS - 1) {
        float local = 0.f;
        for (int r = tid; r < NN; r += NTHR)
            local += (1.0f - g_pos[r]) * INV_TAU + __logf(g_rowsum[r]);
#pragma unroll
        for (int o = 16; o > 0; o >>= 1) local += __shfl_xor_sync(0xFFFFFFFFu, local, o);
        __shared__ float red[16];
        if (lane == 0) red[wid] = local;
        __syncthreads();
        if (tid < 16) {
            float v = red[tid];
#pragma unroll
            for (int o = 8; o > 0; o >>= 1) v += __shfl_xor_sync(0xFFFFu, v, o);
            if (tid == 0) out[0] = v * (1.0f / (float)NN);
        }
    }
}

// ---------------------------------------------------------------------------
extern "C" void kernel_launch(void* const* d_in, const int* in_sizes, int n_in,
                              void* d_out, int out_size) {
    (void)in_sizes; (void)n_in; (void)out_size;
    const float* anchor   = (const float*)d_in[0];
    const float* positive = (const float*)d_in[1];

    cudaFuncSetAttribute(ntx_main, cudaFuncAttributeMaxDynamicSharedMemorySize,
                         SMEM_BYTES);

    ntx_normalize<<<NN / 8, 256>>>(anchor, positive);
    ntx_main<<<NCTAS, NTHR, SMEM_BYTES>>>((float*)d_out);
}